// round 14
// baseline (speedup 1.0000x reference)
#include <cuda_runtime.h>
#include <cuda_fp16.h>
#include <cstdint>
#include <cstddef>

// ---------------- problem dims (fixed for this problem) ----------------
#define DIMD 1024
#define HID  4096
#define MTOK 16384            // 4*4096 tokens
#define KC1  16               // GEMM1 k-chunks of 64 (adapter folded into weights)
#define KC2  64               // GEMM2 k-chunks of 64: 4096
#define TILEB 16384           // one 128x64 fp16 tile, SW128-swizzled

// Chunk-major tile layouts: buf[tileIdx][kchunk][128 rows][128B swizzled row]
// ---------------- device scratch (no cudaMalloc allowed) ----------------
__device__ __align__(1024) __half g_A1[(size_t)(MTOK / 128) * KC1 * TILEB / 2];
__device__ __align__(1024) __half g_B1[(size_t)(HID  / 128) * KC1 * TILEB / 2];
__device__ __align__(1024) __half g_R [(size_t)(MTOK / 128) * KC2 * TILEB / 2];
__device__ __align__(1024) __half g_B2[(size_t)(DIMD / 128) * KC2 * TILEB / 2];
__device__ float g_scale_fc[HID];
__device__ float g_scale_pj[DIMD];
__device__ float g_W[16 * DIMD];            // fast_b @ v  (16 x 1024)

// ---------------- helpers ----------------
__device__ __forceinline__ uint32_t smem_to_u32(const void* p) {
    uint32_t a;
    asm("{ .reg .u64 t; cvta.to.shared.u64 t, %1; cvt.u32.u64 %0, t; }" : "=r"(a) : "l"(p));
    return a;
}
#define SW128(o) ((o) ^ (((o) >> 3) & 0x70))

#define MBARRIER_INIT(mbar, count) \
    asm volatile("mbarrier.init.shared.b64 [%0], %1;" :: "r"((uint32_t)(mbar)), "r"((uint32_t)(count)) : "memory")
#define MBARRIER_EXPECT_TX(mbar, tx) \
    asm volatile("mbarrier.arrive.expect_tx.shared.b64 _, [%0], %1;" :: "r"((uint32_t)(mbar)), "r"((uint32_t)(tx)) : "memory")
#define MBARRIER_ARRIVE(mbar) \
    asm volatile("mbarrier.arrive.shared.b64 _, [%0];" :: "r"((uint32_t)(mbar)) : "memory")

#define MBARRIER_WAIT_PARITY(mbar, par) do { \
    uint32_t _m = (uint32_t)(mbar); uint32_t _p = (uint32_t)(par); uint32_t _d; \
    asm volatile("{\n\t.reg .pred p;\n\t" \
        "mbarrier.try_wait.parity.acquire.cta.shared::cta.b64 p, [%1], %2;\n\t" \
        "selp.b32 %0, 1, 0, p;\n\t}" : "=r"(_d) : "r"(_m), "r"(_p) : "memory"); \
    if (!_d) { \
        asm volatile("{\n\t.reg .pred P1;\n\t" \
            "WL_%=:\n\t" \
            "mbarrier.try_wait.parity.acquire.cta.shared::cta.b64 P1, [%0], %1, 0x989680;\n\t" \
            "@P1 bra.uni WD_%=;\n\tbra.uni WL_%=;\n\tWD_%=:\n\t}" \
            :: "r"(_m), "r"(_p) : "memory"); \
    } \
} while (0)

// bulk async copy GMEM -> SMEM with mbarrier complete_tx (base sm_90 ISA)
__device__ __forceinline__ void bulk_g2s(uint32_t dst, const void* src, uint32_t bytes, uint32_t mbar) {
    asm volatile("cp.async.bulk.shared::cluster.global.mbarrier::complete_tx::bytes [%0], [%1], %2, [%3];"
        :: "r"(dst), "l"(src), "r"(bytes), "r"(mbar) : "memory");
}

__device__ __forceinline__ void ldm_x4(uint32_t addr, uint32_t* r) {
    asm volatile("ldmatrix.sync.aligned.m8n8.x4.shared.b16 {%0,%1,%2,%3}, [%4];"
        : "=r"(r[0]), "=r"(r[1]), "=r"(r[2]), "=r"(r[3]) : "r"(addr));
}
__device__ __forceinline__ void mma16816(float* c, const uint32_t* a, uint32_t b0, uint32_t b1) {
    asm volatile("mma.sync.aligned.m16n8k16.row.col.f32.f16.f16.f32 "
        "{%0,%1,%2,%3}, {%4,%5,%6,%7}, {%8,%9}, {%0,%1,%2,%3};"
        : "+f"(c[0]), "+f"(c[1]), "+f"(c[2]), "+f"(c[3])
        : "r"(a[0]), "r"(a[1]), "r"(a[2]), "r"(a[3]), "r"(b0), "r"(b1));
}

// chunk-major swizzled address (element granularity, returns byte offset)
__device__ __forceinline__ size_t cm_off(int tile, int kc, int nchunks, int row, int col /*fp16 col 0..63*/) {
    return (size_t)(tile * nchunks + kc) * TILEB + SW128((uint32_t)(row * 128 + col * 2));
}

// ============================================================================
// prep kernels (write chunk-major swizzled layouts directly)
// ============================================================================

// W = fast_b @ v  (16 x 1024)
__global__ void compose_w_kernel(const float* __restrict__ fb, const float* __restrict__ v)
{
    int idx = blockIdx.x * blockDim.x + threadIdx.x;
    if (idx >= 16 * DIMD) return;
    int j = idx >> 10, d = idx & 1023;
    float s = 0.f;
#pragma unroll
    for (int r = 0; r < 16; r++) s += fb[j * 16 + r] * v[r * DIMD + d];
    g_W[idx] = s;
}

// per-output-row abs-mean scale -> ternary (+ fused rank-16 adapter delta for
// w_fc: delta_row = gate * u[i,:] @ W, computed into smem on the fly).
// 256 threads per row for latency hiding.
__global__ void pack_w_kernel(const float* __restrict__ w, int K, int Kc,
                              __half* __restrict__ Bq,
                              float* __restrict__ scaleOut,
                              const float* __restrict__ u,
                              const float* __restrict__ gatep)
{
    __shared__ float dsh[1024];
    __shared__ float ur[16];
    __shared__ double red[8];
    __shared__ float scsh;
    int i = blockIdx.x;
    int t = threadIdx.x;  // 256 threads
    const float* wr = w + (size_t)i * K;
    if (u != nullptr) {
        if (t < 16) ur[t] = u[(size_t)i * 16 + t] * (*gatep);
        __syncthreads();
#pragma unroll
        for (int q = 0; q < 4; q++) {
            int j = q * 256 + t;
            float s = 0.f;
#pragma unroll
            for (int r = 0; r < 16; r++) s += ur[r] * g_W[r * DIMD + j];
            dsh[j] = s;
        }
    }
    double s = 0.0;
    for (int j = t; j < K; j += 256) s += fabs((double)wr[j]);
    for (int o = 16; o; o >>= 1) s += __shfl_down_sync(0xffffffffu, s, o);
    if ((t & 31) == 0) red[t >> 5] = s;
    __syncthreads();
    if (t == 0) {
        double tot = 0.0;
#pragma unroll
        for (int q = 0; q < 8; q++) tot += red[q];
        float m = (float)(tot / K);
        scsh = fmaxf(m, 1e-5f);
        scaleOut[i] = scsh;
    }
    __syncthreads();
    float scale = scsh;
    float invs = 1.f / scale;
    char* base = (char*)Bq;
    int tile = i >> 7, row = i & 127;
    for (int j = t; j < K; j += 256) {
        float tern = rintf(wr[j] * invs);
        tern = fminf(fmaxf(tern, -1.f), 1.f);
        if (u != nullptr) tern += dsh[j] * invs;   // folded rank-16 adapter
        *(__half*)(base + cm_off(tile, j >> 6, Kc, row, j & 63)) = __float2half(tern);
    }
}

// x -> fp16 chunk-major A1; 8 elements per thread (16B swizzled chunks are
// contiguous under SW128, so a single uint4 store is valid).
__global__ void prep_x_kernel(const float* __restrict__ x)
{
    size_t idx = (size_t)blockIdx.x * blockDim.x + threadIdx.x;   // oct index
    if (idx >= (size_t)MTOK * DIMD / 8) return;
    size_t m = idx >> 7;                 // token row
    int k = ((int)(idx & 127)) * 8;      // col
    const float4 v0 = *(const float4*)(x + m * DIMD + k);
    const float4 v1 = *(const float4*)(x + m * DIMD + k + 4);
    __half2 h[4];
    h[0] = __floats2half2_rn(v0.x, v0.y);
    h[1] = __floats2half2_rn(v0.z, v0.w);
    h[2] = __floats2half2_rn(v1.x, v1.y);
    h[3] = __floats2half2_rn(v1.z, v1.w);
    *(uint4*)((char*)g_A1 + cm_off((int)(m >> 7), k >> 6, KC1, (int)(m & 127), k & 63)) =
        *(uint4*)h;
}

// ============================================================================
// GEMM: C[128, BN] tile (BN = IM-dependent), fp16 HMMA f32-acc; 256 threads;
// cp.async.bulk + mbarrier ring; 2 CTAs/SM.
//   IM=4 -> BN=128 (warps 2x4, warptile 64x32), per-ks pipelined frags
//   IM=2 -> BN=64  (warps 4x2, warptile 32x32), FULL-CHUNK fragment preload
// B is ALWAYS packed in 128-row tiles; for BN=64 each 128-row tile holds
// SUBT=2 contiguous 8KB subtile halves per 16KB chunk.
// EPI==1: h = scale_n*acc; r=relu(h); rr=r*r; fp16(rr) chunk-major to g_R
// EPI==2: out = scale_n*acc (f32) row-major
// ============================================================================
#define BM 128

template <int EPI, int IM, int NST>
__global__ void __launch_bounds__(256, 2)
gemm_kernel(const __half* __restrict__ A, const __half* __restrict__ B,
            const float* __restrict__ scale, void* __restrict__ out,
            int kChunks, int nTiles)
{
    constexpr int WN   = (IM == 4) ? 4 : 2;       // warps along N
    constexpr int BN   = WN * 32;                 // 128 or 64
    constexpr int BTB  = BN * 128;                // B tile bytes (16K or 8K)
    constexpr int SUBT = 128 / BN;                // subtiles per packed 128-row tile
    constexpr int STB  = TILEB + BTB;             // stage bytes

    extern __shared__ char smem_raw[];
    __shared__ __align__(8) uint64_t mbar_store[2 * NST];
    __shared__ float s_scale[BN];
    const uint32_t DATA = smem_to_u32(smem_raw);
    const uint32_t FULL = smem_to_u32(mbar_store);
    const uint32_t EMPTY = FULL + 8 * NST;
    const int tid = (int)threadIdx.x;
    const int lane = tid & 31;
    const int wid = tid >> 5;
    const int wm = wid / WN;                      // M-slice index
    const int wn = wid % WN;                      // N-slice index
    const int mbase = wm * (IM * 16);
    const int tile_m = (int)blockIdx.x / nTiles;
    const int tile_n = (int)blockIdx.x % nTiles;

    if (tid == 0) {
#pragma unroll
        for (int s = 0; s < NST; s++) {
            MBARRIER_INIT(FULL + 8 * s, 1);
            MBARRIER_INIT(EMPTY + 8 * s, 256);
        }
    }
    __syncthreads();

    const char* Ab = (const char*)A + (size_t)tile_m * kChunks * TILEB;
    // B addressing: 128-row packed tiles; pick the subtile's slice per chunk.
    const char* Bb = (const char*)B
        + (size_t)(tile_n / SUBT) * kChunks * TILEB
        + (size_t)(tile_n % SUBT) * BTB;

    auto produce = [&](int j) {
        int s = j % NST;
        uint32_t dst = DATA + s * STB;
        MBARRIER_EXPECT_TX(FULL + 8 * s, (uint32_t)STB);
        bulk_g2s(dst,         Ab + (size_t)j * TILEB, TILEB, FULL + 8 * s);
        bulk_g2s(dst + TILEB, Bb + (size_t)j * TILEB, BTB,   FULL + 8 * s);
    };

    if (tid == 0) {
        int npre = kChunks < NST ? kChunks : NST;
        for (int j = 0; j < npre; j++) produce(j);
    }

    float acc[IM * 4][4];
#pragma unroll
    for (int i = 0; i < IM * 4; i++)
#pragma unroll
        for (int q = 0; q < 4; q++) acc[i][q] = 0.f;

    const int lr = lane & 15, lc = lane >> 4;

    for (int k = 0; k < kChunks; k++) {
        int s = k % NST;
        int ph = (k / NST) & 1;
        MBARRIER_WAIT_PARITY(FULL + 8 * s, ph);

        uint32_t sA = DATA + s * STB;
        uint32_t sB = sA + TILEB;

        if constexpr (IM == 2) {
            // full-chunk preload: all 16 LDSM first (MLP 16), then 32 HMMA
            uint32_t afr2[4][2][4], bfr2[4][2][4];
#pragma unroll
            for (int ks = 0; ks < 4; ks++) {
                uint32_t bcol = (uint32_t)(ks * 32 + lc * 16);
#pragma unroll
                for (int im = 0; im < 2; im++) {
                    int row = mbase + im * 16 + lr;
                    ldm_x4(sA + SW128((uint32_t)row * 128 + bcol), afr2[ks][im]);
                }
#pragma unroll
                for (int in2 = 0; in2 < 2; in2++) {
                    int row = wn * 32 + in2 * 16 + lr;
                    ldm_x4(sB + SW128((uint32_t)row * 128 + bcol), bfr2[ks][in2]);
                }
            }
#pragma unroll
            for (int ks = 0; ks < 4; ks++)
#pragma unroll
                for (int im = 0; im < 2; im++)
#pragma unroll
                    for (int g = 0; g < 4; g++)
                        mma16816(acc[im * 4 + g], afr2[ks][im],
                                 bfr2[ks][g >> 1][g & 1], bfr2[ks][g >> 1][(g & 1) + 2]);
        } else {
            uint32_t afr[IM][4], bfr[2][4];
#pragma unroll
            for (int ks = 0; ks < 4; ks++) {
                uint32_t bcol = (uint32_t)(ks * 32 + lc * 16);
#pragma unroll
                for (int im = 0; im < IM; im++) {
                    int row = mbase + im * 16 + lr;
                    ldm_x4(sA + SW128((uint32_t)row * 128 + bcol), afr[im]);
                }
#pragma unroll
                for (int in2 = 0; in2 < 2; in2++) {
                    int row = wn * 32 + in2 * 16 + lr;
                    ldm_x4(sB + SW128((uint32_t)row * 128 + bcol), bfr[in2]);
                }
#pragma unroll
                for (int im = 0; im < IM; im++)
#pragma unroll
                    for (int g = 0; g < 4; g++)
                        mma16816(acc[im * 4 + g], afr[im],
                                 bfr[g >> 1][g & 1], bfr[g >> 1][(g & 1) + 2]);
            }
        }
        // release this stage (our smem reads are done)
        MBARRIER_ARRIVE(EMPTY + 8 * s);
        if (tid == 0) {
            int j = k + NST;
            if (j < kChunks) {
                MBARRIER_WAIT_PARITY(EMPTY + 8 * s, ph);
                produce(j);
            }
        }
    }

    // ---- epilogue ----
    if (tid < BN) s_scale[tid] = scale[tile_n * BN + tid];
    __syncthreads();

#pragma unroll
    for (int im = 0; im < IM; im++) {
#pragma unroll
        for (int g = 0; g < 4; g++) {
            const float* c = acc[im * 4 + g];
            int ncol = wn * 32 + g * 8 + (lane & 3) * 2;
            int lrow0 = mbase + im * 16 + (lane >> 2);
            float s0 = s_scale[ncol], s1 = s_scale[ncol + 1];
            if (EPI == 1) {
                int gcol = tile_n * BN + ncol;
                int kc = gcol >> 6, cc = gcol & 63;
#pragma unroll
                for (int half = 0; half < 2; half++) {
                    int lrow = lrow0 + half * 8;
                    float h0 = c[half * 2 + 0] * s0;
                    float h1 = c[half * 2 + 1] * s1;
                    float r0 = fmaxf(h0, 0.f), r1 = fmaxf(h1, 0.f);
                    __half2 hp;
                    hp.x = __float2half(r0 * r0);
                    hp.y = __float2half(r1 * r1);
                    *(__half2*)((char*)g_R + cm_off(tile_m, kc, KC2, lrow, cc)) = hp;
                }
            } else {
#pragma unroll
                for (int half = 0; half < 2; half++) {
                    int row = tile_m * BM + lrow0 + half * 8;
                    float2 v;
                    v.x = c[half * 2 + 0] * s0;
                    v.y = c[half * 2 + 1] * s1;
                    float* orow = (float*)out + (size_t)row * DIMD + tile_n * BN + ncol;
                    *(float2*)orow = v;
                }
            }
        }
    }
}

// ============================================================================
// launch
// ============================================================================
extern "C" void kernel_launch(void* const* d_in, const int* in_sizes, int n_in,
                              void* d_out, int out_size)
{
    const float* x      = (const float*)d_in[0];
    const float* fast_b = (const float*)d_in[1];
    const float* w_fc   = (const float*)d_in[2];
    const float* w_proj = (const float*)d_in[3];
    const float* u      = (const float*)d_in[4];
    const float* v      = (const float*)d_in[5];
    const float* gate   = (const float*)d_in[6];

    void *pA1, *pB1, *pR, *pB2, *pSfc, *pSpj;
    cudaGetSymbolAddress(&pA1, g_A1);
    cudaGetSymbolAddress(&pB1, g_B1);
    cudaGetSymbolAddress(&pR,  g_R);
    cudaGetSymbolAddress(&pB2, g_B2);
    cudaGetSymbolAddress(&pSfc, g_scale_fc);
    cudaGetSymbolAddress(&pSpj, g_scale_pj);

    // GEMM1: 128x128 tiles, 3 stages (32KB/stage) -> 96KB, 2 CTAs/SM
    constexpr int SMEM1 = 3 * (TILEB + 128 * 128);
    // GEMM2: 128x64 tiles, 4 stages (24KB/stage) -> 96KB, 2 CTAs/SM
    constexpr int SMEM2 = 4 * (TILEB + 64 * 128);
    cudaFuncSetAttribute((const void*)gemm_kernel<1, 4, 3>, cudaFuncAttributeMaxDynamicSharedMemorySize, SMEM1);
    cudaFuncSetAttribute((const void*)gemm_kernel<2, 2, 4>, cudaFuncAttributeMaxDynamicSharedMemorySize, SMEM2);

    // prep
    compose_w_kernel<<<(16 * DIMD + 255) / 256, 256>>>(fast_b, v);
    pack_w_kernel<<<HID, 256>>>(w_fc, DIMD, KC1, (__half*)pB1, (float*)pSfc, u, gate);
    pack_w_kernel<<<DIMD, 256>>>(w_proj, HID, KC2, (__half*)pB2, (float*)pSpj, nullptr, nullptr);
    prep_x_kernel<<<(MTOK * DIMD / 8 + 255) / 256, 256>>>(x);

    // GEMM1: [16384 x 4096] = A1 @ B1^T  (+ relu^2), K = 16*64, BN=128
    gemm_kernel<1, 4, 3><<<(MTOK / BM) * (HID / 128), 256, SMEM1>>>(
        (const __half*)pA1, (const __half*)pB1,
        (const float*)pSfc, pR, KC1, HID / 128);

    // GEMM2: out[16384 x 1024] = R @ B2^T, K = 64*64, BN=64
    gemm_kernel<2, 2, 4><<<(MTOK / BM) * (DIMD / 64), 256, SMEM2>>>(
        (const __half*)pR, (const __half*)pB2,
        (const float*)pSpj, d_out, KC2, DIMD / 64);
}

// round 17
// speedup vs baseline: 1.0241x; 1.0241x over previous
#include <cuda_runtime.h>
#include <cuda_fp16.h>
#include <cstdint>
#include <cstddef>

// ---------------- problem dims (fixed for this problem) ----------------
#define DIMD 1024
#define HID  4096
#define MTOK 16384            // 4*4096 tokens
#define KC1  16               // GEMM1 k-chunks of 64 (adapter folded into weights)
#define KC2  64               // GEMM2 k-chunks of 64: 4096
#define TILEB 16384           // one 128x64 fp16 tile, SW128-swizzled

// Chunk-major tile layouts: buf[tileIdx][kchunk][128 rows][128B swizzled row]
// ---------------- device scratch (no cudaMalloc allowed) ----------------
__device__ __align__(1024) __half g_A1[(size_t)(MTOK / 128) * KC1 * TILEB / 2];
__device__ __align__(1024) __half g_B1[(size_t)(HID  / 128) * KC1 * TILEB / 2];
__device__ __align__(1024) __half g_R [(size_t)(MTOK / 128) * KC2 * TILEB / 2];
__device__ __align__(1024) __half g_B2[(size_t)(DIMD / 128) * KC2 * TILEB / 2];
__device__ float g_scale_fc[HID];
__device__ float g_scale_pj[DIMD];
__device__ float g_W[16 * DIMD];            // fast_b @ v  (16 x 1024)

// ---------------- helpers ----------------
__device__ __forceinline__ uint32_t smem_to_u32(const void* p) {
    uint32_t a;
    asm("{ .reg .u64 t; cvta.to.shared.u64 t, %1; cvt.u32.u64 %0, t; }" : "=r"(a) : "l"(p));
    return a;
}
#define SW128(o) ((o) ^ (((o) >> 3) & 0x70))

#define MBARRIER_INIT(mbar, count) \
    asm volatile("mbarrier.init.shared.b64 [%0], %1;" :: "r"((uint32_t)(mbar)), "r"((uint32_t)(count)) : "memory")
#define MBARRIER_EXPECT_TX(mbar, tx) \
    asm volatile("mbarrier.arrive.expect_tx.shared.b64 _, [%0], %1;" :: "r"((uint32_t)(mbar)), "r"((uint32_t)(tx)) : "memory")
#define MBARRIER_ARRIVE(mbar) \
    asm volatile("mbarrier.arrive.shared.b64 _, [%0];" :: "r"((uint32_t)(mbar)) : "memory")

#define MBARRIER_WAIT_PARITY(mbar, par) do { \
    uint32_t _m = (uint32_t)(mbar); uint32_t _p = (uint32_t)(par); uint32_t _d; \
    asm volatile("{\n\t.reg .pred p;\n\t" \
        "mbarrier.try_wait.parity.acquire.cta.shared::cta.b64 p, [%1], %2;\n\t" \
        "selp.b32 %0, 1, 0, p;\n\t}" : "=r"(_d) : "r"(_m), "r"(_p) : "memory"); \
    if (!_d) { \
        asm volatile("{\n\t.reg .pred P1;\n\t" \
            "WL_%=:\n\t" \
            "mbarrier.try_wait.parity.acquire.cta.shared::cta.b64 P1, [%0], %1, 0x989680;\n\t" \
            "@P1 bra.uni WD_%=;\n\tbra.uni WL_%=;\n\tWD_%=:\n\t}" \
            :: "r"(_m), "r"(_p) : "memory"); \
    } \
} while (0)

// bulk async copy GMEM -> SMEM with mbarrier complete_tx (base sm_90 ISA)
__device__ __forceinline__ void bulk_g2s(uint32_t dst, const void* src, uint32_t bytes, uint32_t mbar) {
    asm volatile("cp.async.bulk.shared::cluster.global.mbarrier::complete_tx::bytes [%0], [%1], %2, [%3];"
        :: "r"(dst), "l"(src), "r"(bytes), "r"(mbar) : "memory");
}

__device__ __forceinline__ void ldm_x4(uint32_t addr, uint32_t* r) {
    asm volatile("ldmatrix.sync.aligned.m8n8.x4.shared.b16 {%0,%1,%2,%3}, [%4];"
        : "=r"(r[0]), "=r"(r[1]), "=r"(r[2]), "=r"(r[3]) : "r"(addr));
}
__device__ __forceinline__ void mma16816(float* c, const uint32_t* a, uint32_t b0, uint32_t b1) {
    asm volatile("mma.sync.aligned.m16n8k16.row.col.f32.f16.f16.f32 "
        "{%0,%1,%2,%3}, {%4,%5,%6,%7}, {%8,%9}, {%0,%1,%2,%3};"
        : "+f"(c[0]), "+f"(c[1]), "+f"(c[2]), "+f"(c[3])
        : "r"(a[0]), "r"(a[1]), "r"(a[2]), "r"(a[3]), "r"(b0), "r"(b1));
}

// chunk-major swizzled address (element granularity, returns byte offset)
__device__ __forceinline__ size_t cm_off(int tile, int kc, int nchunks, int row, int col /*fp16 col 0..63*/) {
    return (size_t)(tile * nchunks + kc) * TILEB + SW128((uint32_t)(row * 128 + col * 2));
}

// ============================================================================
// prep kernels
// ============================================================================

// W = fast_b @ v  (16 x 1024)
__global__ void compose_w_kernel(const float* __restrict__ fb, const float* __restrict__ v)
{
    int idx = blockIdx.x * blockDim.x + threadIdx.x;
    if (idx >= 16 * DIMD) return;
    int j = idx >> 10, d = idx & 1023;
    float s = 0.f;
#pragma unroll
    for (int r = 0; r < 16; r++) s += fb[j * 16 + r] * v[r * DIMD + d];
    g_W[idx] = s;
}

// per-output-row pack body: abs-mean scale (f64 reduction — REQUIRED; ternary
// rounding is discontinuous at |w|/scale=0.5) -> ternary (+ optional fused
// rank-16 adapter delta). 256 threads per row. Identical math to R14 (passed).
__device__ __forceinline__ void pack_row(const float* __restrict__ wr, int K, int Kc,
                                         __half* __restrict__ Bq, int i,
                                         float* __restrict__ scaleOut,
                                         const float* __restrict__ u,
                                         const float* __restrict__ gatep,
                                         float* dsh, float* ur, double* red, float* scsh)
{
    int t = threadIdx.x;  // 256 threads
    if (u != nullptr) {
        if (t < 16) ur[t] = u[(size_t)i * 16 + t] * (*gatep);
        __syncthreads();
#pragma unroll
        for (int q = 0; q < 4; q++) {
            int j = q * 256 + t;
            float s = 0.f;
#pragma unroll
            for (int r = 0; r < 16; r++) s += ur[r] * g_W[r * DIMD + j];
            dsh[j] = s;
        }
    }
    double s = 0.0;
    for (int j = t; j < K; j += 256) s += fabs((double)wr[j]);
    for (int o = 16; o; o >>= 1) s += __shfl_down_sync(0xffffffffu, s, o);
    if ((t & 31) == 0) red[t >> 5] = s;
    __syncthreads();
    if (t == 0) {
        double tot = 0.0;
#pragma unroll
        for (int q = 0; q < 8; q++) tot += red[q];
        float m = (float)(tot / K);
        *scsh = fmaxf(m, 1e-5f);
        scaleOut[i] = *scsh;
    }
    __syncthreads();
    float invs = 1.f / *scsh;
    char* base = (char*)Bq;
    int tile = i >> 7, row = i & 127;
    for (int j = t; j < K; j += 256) {
        float tern = rintf(wr[j] * invs);
        tern = fminf(fmaxf(tern, -1.f), 1.f);
        if (u != nullptr) tern += dsh[j] * invs;   // folded rank-16 adapter
        *(__half*)(base + cm_off(tile, j >> 6, Kc, row, j & 63)) = __float2half(tern);
    }
}

#define XBLOCKS (MTOK * DIMD / 8 / 256)   // 8192

// fused prep: blocks [0,HID) pack w_fc rows; [HID, HID+DIMD) pack w_proj rows;
// [HID+DIMD, HID+DIMD+XBLOCKS) convert x -> fp16 chunk-major A1.
__global__ void __launch_bounds__(256)
prep_all_kernel(const float* __restrict__ w_fc, const float* __restrict__ w_proj,
                const float* __restrict__ x,
                const float* __restrict__ u, const float* __restrict__ gatep,
                __half* __restrict__ B1, __half* __restrict__ B2,
                float* __restrict__ sfc, float* __restrict__ spj)
{
    __shared__ float dsh[1024];
    __shared__ float ur[16];
    __shared__ double red[8];
    __shared__ float scsh;
    int bid = blockIdx.x;
    if (bid < HID) {
        pack_row(w_fc + (size_t)bid * DIMD, DIMD, KC1, B1, bid, sfc, u, gatep,
                 dsh, ur, red, &scsh);
    } else if (bid < HID + DIMD) {
        int i = bid - HID;
        pack_row(w_proj + (size_t)i * HID, HID, KC2, B2, i, spj, nullptr, nullptr,
                 dsh, ur, red, &scsh);
    } else {
        size_t idx = (size_t)(bid - (HID + DIMD)) * 256 + threadIdx.x;  // oct index
        size_t m = idx >> 7;                 // token row
        int k = ((int)(idx & 127)) * 8;      // col
        const float4 v0 = *(const float4*)(x + m * DIMD + k);
        const float4 v1 = *(const float4*)(x + m * DIMD + k + 4);
        __half2 h[4];
        h[0] = __floats2half2_rn(v0.x, v0.y);
        h[1] = __floats2half2_rn(v0.z, v0.w);
        h[2] = __floats2half2_rn(v1.x, v1.y);
        h[3] = __floats2half2_rn(v1.z, v1.w);
        *(uint4*)((char*)g_A1 + cm_off((int)(m >> 7), k >> 6, KC1, (int)(m & 127), k & 63)) =
            *(uint4*)h;
    }
}

// ============================================================================
// GEMM: C[128, BN] tile (BN = IM-dependent), fp16 HMMA f32-acc; 256 threads;
// cp.async.bulk + mbarrier ring; 2 CTAs/SM.  (bit-identical to R13, best known)
//   IM=4 -> BN=128 (warps 2x4, warptile 64x32)
//   IM=2 -> BN=64  (warps 4x2, warptile 32x32)
// B is ALWAYS packed in 128-row tiles; for BN=64 each 128-row tile holds
// SUBT=2 contiguous 8KB subtile halves per 16KB chunk.
// EPI==1: h = scale_n*acc; r=relu(h); rr=r*r; fp16(rr) chunk-major to g_R
// EPI==2: out = scale_n*acc (f32) row-major
// ============================================================================
#define BM 128

template <int EPI, int IM, int NST>
__global__ void __launch_bounds__(256, 2)
gemm_kernel(const __half* __restrict__ A, const __half* __restrict__ B,
            const float* __restrict__ scale, void* __restrict__ out,
            int kChunks, int nTiles)
{
    constexpr int WN   = (IM == 4) ? 4 : 2;       // warps along N
    constexpr int BN   = WN * 32;                 // 128 or 64
    constexpr int BTB  = BN * 128;                // B tile bytes (16K or 8K)
    constexpr int SUBT = 128 / BN;                // subtiles per packed 128-row tile
    constexpr int STB  = TILEB + BTB;             // stage bytes

    extern __shared__ char smem_raw[];
    __shared__ __align__(8) uint64_t mbar_store[2 * NST];
    __shared__ float s_scale[BN];
    const uint32_t DATA = smem_to_u32(smem_raw);
    const uint32_t FULL = smem_to_u32(mbar_store);
    const uint32_t EMPTY = FULL + 8 * NST;
    const int tid = (int)threadIdx.x;
    const int lane = tid & 31;
    const int wid = tid >> 5;
    const int wm = wid / WN;                      // M-slice index
    const int wn = wid % WN;                      // N-slice index
    const int mbase = wm * (IM * 16);
    const int tile_m = (int)blockIdx.x / nTiles;
    const int tile_n = (int)blockIdx.x % nTiles;

    if (tid == 0) {
#pragma unroll
        for (int s = 0; s < NST; s++) {
            MBARRIER_INIT(FULL + 8 * s, 1);
            MBARRIER_INIT(EMPTY + 8 * s, 256);
        }
    }
    __syncthreads();

    const char* Ab = (const char*)A + (size_t)tile_m * kChunks * TILEB;
    // B addressing: 128-row packed tiles; pick the subtile's slice per chunk.
    const char* Bb = (const char*)B
        + (size_t)(tile_n / SUBT) * kChunks * TILEB
        + (size_t)(tile_n % SUBT) * BTB;

    auto produce = [&](int j) {
        int s = j % NST;
        uint32_t dst = DATA + s * STB;
        MBARRIER_EXPECT_TX(FULL + 8 * s, (uint32_t)STB);
        bulk_g2s(dst,         Ab + (size_t)j * TILEB, TILEB, FULL + 8 * s);
        bulk_g2s(dst + TILEB, Bb + (size_t)j * TILEB, BTB,   FULL + 8 * s);
    };

    if (tid == 0) {
        int npre = kChunks < NST ? kChunks : NST;
        for (int j = 0; j < npre; j++) produce(j);
    }

    float acc[IM * 4][4];
#pragma unroll
    for (int i = 0; i < IM * 4; i++)
#pragma unroll
        for (int q = 0; q < 4; q++) acc[i][q] = 0.f;

    const int lr = lane & 15, lc = lane >> 4;
    uint32_t afr[IM][4], bfr[2][4];

    for (int k = 0; k < kChunks; k++) {
        int s = k % NST;
        int ph = (k / NST) & 1;
        MBARRIER_WAIT_PARITY(FULL + 8 * s, ph);

        uint32_t sA = DATA + s * STB;
        uint32_t sB = sA + TILEB;

#pragma unroll
        for (int ks = 0; ks < 4; ks++) {
            uint32_t bcol = (uint32_t)(ks * 32 + lc * 16);
#pragma unroll
            for (int im = 0; im < IM; im++) {
                int row = mbase + im * 16 + lr;
                ldm_x4(sA + SW128((uint32_t)row * 128 + bcol), afr[im]);
            }
#pragma unroll
            for (int in2 = 0; in2 < 2; in2++) {
                int row = wn * 32 + in2 * 16 + lr;
                ldm_x4(sB + SW128((uint32_t)row * 128 + bcol), bfr[in2]);
            }
#pragma unroll
            for (int im = 0; im < IM; im++)
#pragma unroll
                for (int g = 0; g < 4; g++)
                    mma16816(acc[im * 4 + g], afr[im],
                             bfr[g >> 1][g & 1], bfr[g >> 1][(g & 1) + 2]);
        }
        // release this stage (our smem reads are done)
        MBARRIER_ARRIVE(EMPTY + 8 * s);
        if (tid == 0) {
            int j = k + NST;
            if (j < kChunks) {
                MBARRIER_WAIT_PARITY(EMPTY + 8 * s, ph);
                produce(j);
            }
        }
    }

    // ---- epilogue ----
    if (tid < BN) s_scale[tid] = scale[tile_n * BN + tid];
    __syncthreads();

#pragma unroll
    for (int im = 0; im < IM; im++) {
#pragma unroll
        for (int g = 0; g < 4; g++) {
            const float* c = acc[im * 4 + g];
            int ncol = wn * 32 + g * 8 + (lane & 3) * 2;
            int lrow0 = mbase + im * 16 + (lane >> 2);
            float s0 = s_scale[ncol], s1 = s_scale[ncol + 1];
            if (EPI == 1) {
                int gcol = tile_n * BN + ncol;
                int kc = gcol >> 6, cc = gcol & 63;
#pragma unroll
                for (int half = 0; half < 2; half++) {
                    int lrow = lrow0 + half * 8;
                    float h0 = c[half * 2 + 0] * s0;
                    float h1 = c[half * 2 + 1] * s1;
                    float r0 = fmaxf(h0, 0.f), r1 = fmaxf(h1, 0.f);
                    __half2 hp;
                    hp.x = __float2half(r0 * r0);
                    hp.y = __float2half(r1 * r1);
                    *(__half2*)((char*)g_R + cm_off(tile_m, kc, KC2, lrow, cc)) = hp;
                }
            } else {
#pragma unroll
                for (int half = 0; half < 2; half++) {
                    int row = tile_m * BM + lrow0 + half * 8;
                    float2 v;
                    v.x = c[half * 2 + 0] * s0;
                    v.y = c[half * 2 + 1] * s1;
                    float* orow = (float*)out + (size_t)row * DIMD + tile_n * BN + ncol;
                    *(float2*)orow = v;
                }
            }
        }
    }
}

// ============================================================================
// launch
// ============================================================================
extern "C" void kernel_launch(void* const* d_in, const int* in_sizes, int n_in,
                              void* d_out, int out_size)
{
    const float* x      = (const float*)d_in[0];
    const float* fast_b = (const float*)d_in[1];
    const float* w_fc   = (const float*)d_in[2];
    const float* w_proj = (const float*)d_in[3];
    const float* u      = (const float*)d_in[4];
    const float* v      = (const float*)d_in[5];
    const float* gate   = (const float*)d_in[6];

    void *pA1, *pB1, *pR, *pB2, *pSfc, *pSpj;
    cudaGetSymbolAddress(&pA1, g_A1);
    cudaGetSymbolAddress(&pB1, g_B1);
    cudaGetSymbolAddress(&pR,  g_R);
    cudaGetSymbolAddress(&pB2, g_B2);
    cudaGetSymbolAddress(&pSfc, g_scale_fc);
    cudaGetSymbolAddress(&pSpj, g_scale_pj);

    // GEMM1: 128x128 tiles, 3 stages (32KB/stage) -> 96KB, 2 CTAs/SM
    constexpr int SMEM1 = 3 * (TILEB + 128 * 128);
    // GEMM2: 128x64 tiles, 4 stages (24KB/stage) -> 96KB, 2 CTAs/SM
    constexpr int SMEM2 = 4 * (TILEB + 64 * 128);
    cudaFuncSetAttribute((const void*)gemm_kernel<1, 4, 3>, cudaFuncAttributeMaxDynamicSharedMemorySize, SMEM1);
    cudaFuncSetAttribute((const void*)gemm_kernel<2, 2, 4>, cudaFuncAttributeMaxDynamicSharedMemorySize, SMEM2);

    // prep: compose W, then one fused kernel for both weight packs + x convert
    compose_w_kernel<<<(16 * DIMD + 255) / 256, 256>>>(fast_b, v);
    prep_all_kernel<<<HID + DIMD + XBLOCKS, 256>>>(
        w_fc, w_proj, x, u, gate,
        (__half*)pB1, (__half*)pB2, (float*)pSfc, (float*)pSpj);

    // GEMM1: [16384 x 4096] = A1 @ B1^T  (+ relu^2), K = 16*64, BN=128
    gemm_kernel<1, 4, 3><<<(MTOK / BM) * (HID / 128), 256, SMEM1>>>(
        (const __half*)pA1, (const __half*)pB1,
        (const float*)pSfc, pR, KC1, HID / 128);

    // GEMM2: out[16384 x 1024] = R @ B2^T, K = 64*64, BN=64, 2 CTAs/SM
    gemm_kernel<2, 2, 4><<<(MTOK / BM) * (DIMD / 64), 256, SMEM2>>>(
        (const __half*)pR, (const __half*)pB2,
        (const float*)pSpj, d_out, KC2, DIMD / 64);
}